// round 1
// baseline (speedup 1.0000x reference)
#include <cuda_runtime.h>

// Problem dims
#define B_ 2
#define N_ 512
#define T_ 12
#define E_ 128
#define H_ 8
#define D_ 16
#define BHT 192                // B*H*T
#define SLICE 8192             // N*D
#define HEADSZ (BHT*SLICE)     // 1,572,864 floats per head tensor
#define MROWS (B_*N_*T_)       // 12288

// Scratch: heads layout [B,H,T,N,D]
// 0:Qf 1:Kf 2:Vf 3:Qs 4:Ks 5:Vs 6:Qfs
__device__ float g_heads[7][HEADSZ];
__device__ float g_ctx[4][HEADSZ];

struct ProjArgs {
    const float* x[6];
    const float* w[6];
    const float* kj;
    const float* vfp;
};

// ---------------------------------------------------------------------------
// Kernel 1: input projections. y = x @ W, scatter to heads layout.
// Block: 256 threads, tile = 64 rows x 128 cols, W fully in smem.
// ---------------------------------------------------------------------------
__global__ __launch_bounds__(256) void proj_kernel(ProjArgs args) {
    extern __shared__ float sm[];
    float* Ws = sm;             // 128*128
    float* Xs = sm + 128 * 128; // 64*128
    const int p = blockIdx.y;
    const int tile = blockIdx.x;
    const int tid = threadIdx.x;

    const float* W = args.w[p];
    const float* X = args.x[p] + (size_t)tile * 64 * 128;

    for (int i = tid; i < 4096; i += 256)
        ((float4*)Ws)[i] = ((const float4*)W)[i];
    for (int i = tid; i < 2048; i += 256)
        ((float4*)Xs)[i] = ((const float4*)X)[i];
    __syncthreads();

    const int rg = tid >> 4, cg = tid & 15;
    const int r0 = rg << 2, c0 = cg << 3;

    float acc[4][8];
#pragma unroll
    for (int i = 0; i < 4; i++)
#pragma unroll
        for (int j = 0; j < 8; j++) acc[i][j] = 0.f;

#pragma unroll 4
    for (int k = 0; k < 128; k++) {
        float4 w0 = *(const float4*)&Ws[k * 128 + c0];
        float4 w1 = *(const float4*)&Ws[k * 128 + c0 + 4];
#pragma unroll
        for (int i = 0; i < 4; i++) {
            float a = Xs[(r0 + i) * 128 + k];
            acc[i][0] = fmaf(a, w0.x, acc[i][0]);
            acc[i][1] = fmaf(a, w0.y, acc[i][1]);
            acc[i][2] = fmaf(a, w0.z, acc[i][2]);
            acc[i][3] = fmaf(a, w0.w, acc[i][3]);
            acc[i][4] = fmaf(a, w1.x, acc[i][4]);
            acc[i][5] = fmaf(a, w1.y, acc[i][5]);
            acc[i][6] = fmaf(a, w1.z, acc[i][6]);
            acc[i][7] = fmaf(a, w1.w, acc[i][7]);
        }
    }

    const bool isQs = (p == 3);
#pragma unroll
    for (int i = 0; i < 4; i++) {
        int row = tile * 64 + r0 + i;
        int t = row % T_;
        int n = (row / T_) % N_;
        int b = row / (T_ * N_);
        float kj = 0.f, vfpi = 1.f;
        if (isQs) { kj = args.kj[n]; vfpi = args.vfp[n] + 1e-5f; }
#pragma unroll
        for (int j = 0; j < 8; j++) {
            int c = c0 + j;
            int h = c >> 4, d = c & 15;
            int idx = (((b * H_ + h) * T_ + t) * N_ + n) * D_ + d;
            float v = acc[i][j];
            g_heads[p][idx] = v;
            if (isQs) g_heads[6][idx] = kj * (v - v * v / vfpi);
        }
    }
}

// ---------------------------------------------------------------------------
// Kernel 2: attention. One block per (slice, att). 512 threads.
// Per query row: 8 threads, m strided by 8. Scores staged in a private smem
// strip (conflict-free pitches), shuffle reductions for softmax + ctx.
// ---------------------------------------------------------------------------
__global__ __launch_bounds__(512) void attn_kernel() {
    extern __shared__ float sm[];
    float* Bs = sm;                  // 512 * 20
    float* Vsm = sm + 512 * 20;      // 512 * 20
    float* Sc = sm + 2 * 512 * 20;   // 64 * 520

    const int slice = blockIdx.x;    // 0..191
    const int att = blockIdx.y;      // 0..3

    int ai, bi, vi;
    switch (att) {
        case 0:  ai = 0; bi = 1; vi = 2; break;  // ff: Qf,Kf,Vf
        case 1:  ai = 1; bi = 6; vi = 2; break;  // fs: Kf,Qfs,Vf
        case 2:  ai = 4; bi = 0; vi = 5; break;  // sf: Ks,Qf,Vs
        default: ai = 3; bi = 4; vi = 5; break;  // ss: Qs,Ks,Vs
    }

    const float* Ag = g_heads[ai] + slice * SLICE;
    const float* Bg = g_heads[bi] + slice * SLICE;
    const float* Vg = g_heads[vi] + slice * SLICE;
    float* Og = g_ctx[att] + slice * SLICE;

    const int tid = threadIdx.x;
    for (int i = tid; i < 2048; i += 512) {
        int r = i >> 2, s = i & 3;
        float4 bv = ((const float4*)Bg)[i];
        *(float4*)&Bs[r * 20 + s * 4] = bv;
        float4 vv = ((const float4*)Vg)[i];
        *(float4*)&Vsm[r * 20 + s * 4] = vv;
    }
    __syncthreads();

    const int n_local = tid >> 3;   // 0..63
    const int q = tid & 7;          // 0..7
    const int sbase = n_local * 520;

    for (int nc = 0; nc < 8; nc++) {
        const int n = nc * 64 + n_local;
        const float4* Ar = (const float4*)(Ag + n * 16);
        float4 a0 = Ar[0], a1 = Ar[1], a2 = Ar[2], a3 = Ar[3];

        // Phase 1: scores (scaled) + running max
        float mx = -3.0e38f;
#pragma unroll 4
        for (int i = 0; i < 64; i++) {
            int m = q + 8 * i;
            const float* br = &Bs[m * 20];
            float4 b0 = *(const float4*)(br);
            float4 b1 = *(const float4*)(br + 4);
            float4 b2 = *(const float4*)(br + 8);
            float4 b3 = *(const float4*)(br + 12);
            float p0 = fmaf(a0.x, b0.x, fmaf(a0.y, b0.y, fmaf(a0.z, b0.z, a0.w * b0.w)));
            float p1 = fmaf(a1.x, b1.x, fmaf(a1.y, b1.y, fmaf(a1.z, b1.z, a1.w * b1.w)));
            float p2 = fmaf(a2.x, b2.x, fmaf(a2.y, b2.y, fmaf(a2.z, b2.z, a2.w * b2.w)));
            float p3 = fmaf(a3.x, b3.x, fmaf(a3.y, b3.y, fmaf(a3.z, b3.z, a3.w * b3.w)));
            float s = ((p0 + p1) + (p2 + p3)) * 0.25f;
            Sc[sbase + m] = s;
            mx = fmaxf(mx, s);
        }
        mx = fmaxf(mx, __shfl_xor_sync(0xffffffffu, mx, 1));
        mx = fmaxf(mx, __shfl_xor_sync(0xffffffffu, mx, 2));
        mx = fmaxf(mx, __shfl_xor_sync(0xffffffffu, mx, 4));

        // Phase 2: exp + sum
        float sum = 0.f;
#pragma unroll 4
        for (int i = 0; i < 64; i++) {
            int m = q + 8 * i;
            float pe = __expf(Sc[sbase + m] - mx);
            Sc[sbase + m] = pe;
            sum += pe;
        }
        sum += __shfl_xor_sync(0xffffffffu, sum, 1);
        sum += __shfl_xor_sync(0xffffffffu, sum, 2);
        sum += __shfl_xor_sync(0xffffffffu, sum, 4);
        float inv = 1.0f / sum;

        // Phase 3: ctx = p @ V
        float acc[16];
#pragma unroll
        for (int d = 0; d < 16; d++) acc[d] = 0.f;
#pragma unroll 4
        for (int i = 0; i < 64; i++) {
            int m = q + 8 * i;
            float pv = Sc[sbase + m];
            const float* vr = &Vsm[m * 20];
            float4 v0 = *(const float4*)(vr);
            float4 v1 = *(const float4*)(vr + 4);
            float4 v2 = *(const float4*)(vr + 8);
            float4 v3 = *(const float4*)(vr + 12);
            acc[0]  = fmaf(pv, v0.x, acc[0]);
            acc[1]  = fmaf(pv, v0.y, acc[1]);
            acc[2]  = fmaf(pv, v0.z, acc[2]);
            acc[3]  = fmaf(pv, v0.w, acc[3]);
            acc[4]  = fmaf(pv, v1.x, acc[4]);
            acc[5]  = fmaf(pv, v1.y, acc[5]);
            acc[6]  = fmaf(pv, v1.z, acc[6]);
            acc[7]  = fmaf(pv, v1.w, acc[7]);
            acc[8]  = fmaf(pv, v2.x, acc[8]);
            acc[9]  = fmaf(pv, v2.y, acc[9]);
            acc[10] = fmaf(pv, v2.z, acc[10]);
            acc[11] = fmaf(pv, v2.w, acc[11]);
            acc[12] = fmaf(pv, v3.x, acc[12]);
            acc[13] = fmaf(pv, v3.y, acc[13]);
            acc[14] = fmaf(pv, v3.z, acc[14]);
            acc[15] = fmaf(pv, v3.w, acc[15]);
        }
#pragma unroll
        for (int d = 0; d < 16; d++) {
            acc[d] += __shfl_xor_sync(0xffffffffu, acc[d], 1);
            acc[d] += __shfl_xor_sync(0xffffffffu, acc[d], 2);
            acc[d] += __shfl_xor_sync(0xffffffffu, acc[d], 4);
        }
        if (q == 0) {
            float4* op = (float4*)(Og + n * 16);
            op[0] = make_float4(inv * acc[0],  inv * acc[1],  inv * acc[2],  inv * acc[3]);
            op[1] = make_float4(inv * acc[4],  inv * acc[5],  inv * acc[6],  inv * acc[7]);
            op[2] = make_float4(inv * acc[8],  inv * acc[9],  inv * acc[10], inv * acc[11]);
            op[3] = make_float4(inv * acc[12], inv * acc[13], inv * acc[14], inv * acc[15]);
        }
    }
}

// ---------------------------------------------------------------------------
// Kernel 3: output projection. Gather ctx -> [B,N,T,E] rows, GEMM with Wout,
// add bias, write concatenated (ff, fs, sf, ss) output.
// ---------------------------------------------------------------------------
__global__ __launch_bounds__(256) void outproj_kernel(
    const float* __restrict__ Wout, const float* __restrict__ bout,
    float* __restrict__ out) {
    extern __shared__ float sm[];
    float* Ws = sm;             // 128*128
    float* Xs = sm + 128 * 128; // 64*128
    const int att = blockIdx.y;
    const int tile = blockIdx.x;
    const int tid = threadIdx.x;

    for (int i = tid; i < 4096; i += 256)
        ((float4*)Ws)[i] = ((const float4*)Wout)[i];

    const float* ctx = g_ctx[att];
    for (int i = tid; i < 2048; i += 256) {
        int rr = i >> 5;
        int f4 = i & 31;
        int row = tile * 64 + rr;
        int t = row % T_;
        int n = (row / T_) % N_;
        int b = row / (T_ * N_);
        int h = f4 >> 2;
        int ds = (f4 & 3) << 2;
        int idx = (((b * H_ + h) * T_ + t) * N_ + n) * D_ + ds;
        *(float4*)&Xs[rr * 128 + (f4 << 2)] = *(const float4*)&ctx[idx];
    }
    __syncthreads();

    const int rg = tid >> 4, cg = tid & 15;
    const int r0 = rg << 2, c0 = cg << 3;

    float acc[4][8];
#pragma unroll
    for (int i = 0; i < 4; i++)
#pragma unroll
        for (int j = 0; j < 8; j++) acc[i][j] = 0.f;

#pragma unroll 4
    for (int k = 0; k < 128; k++) {
        float4 w0 = *(const float4*)&Ws[k * 128 + c0];
        float4 w1 = *(const float4*)&Ws[k * 128 + c0 + 4];
#pragma unroll
        for (int i = 0; i < 4; i++) {
            float a = Xs[(r0 + i) * 128 + k];
            acc[i][0] = fmaf(a, w0.x, acc[i][0]);
            acc[i][1] = fmaf(a, w0.y, acc[i][1]);
            acc[i][2] = fmaf(a, w0.z, acc[i][2]);
            acc[i][3] = fmaf(a, w0.w, acc[i][3]);
            acc[i][4] = fmaf(a, w1.x, acc[i][4]);
            acc[i][5] = fmaf(a, w1.y, acc[i][5]);
            acc[i][6] = fmaf(a, w1.z, acc[i][6]);
            acc[i][7] = fmaf(a, w1.w, acc[i][7]);
        }
    }

    float bb[8];
#pragma unroll
    for (int j = 0; j < 8; j++) bb[j] = __ldg(&bout[c0 + j]);

    float* outp = out + (size_t)att * MROWS * E_;
#pragma unroll
    for (int i = 0; i < 4; i++) {
        int row = tile * 64 + r0 + i;
#pragma unroll
        for (int j = 0; j < 8; j++) {
            outp[row * 128 + c0 + j] = acc[i][j] + bb[j];
        }
    }
}

// ---------------------------------------------------------------------------
extern "C" void kernel_launch(void* const* d_in, const int* in_sizes, int n_in,
                              void* d_out, int out_size) {
    ProjArgs pa;
    for (int i = 0; i < 6; i++) {
        pa.x[i] = (const float*)d_in[i];
        pa.w[i] = (const float*)d_in[6 + i];
    }
    pa.kj  = (const float*)d_in[12];
    pa.vfp = (const float*)d_in[13];
    const float* Wout = (const float*)d_in[14];
    const float* bout = (const float*)d_in[15];
    float* out = (float*)d_out;

    const int smemProj = (128 * 128 + 64 * 128) * 4;       // 98304 B
    const int smemAttn = (2 * 512 * 20 + 64 * 520) * 4;    // 215040 B

    cudaFuncSetAttribute(proj_kernel, cudaFuncAttributeMaxDynamicSharedMemorySize, smemProj);
    cudaFuncSetAttribute(attn_kernel, cudaFuncAttributeMaxDynamicSharedMemorySize, smemAttn);
    cudaFuncSetAttribute(outproj_kernel, cudaFuncAttributeMaxDynamicSharedMemorySize, smemProj);

    proj_kernel<<<dim3(192, 6), 256, smemProj>>>(pa);
    attn_kernel<<<dim3(192, 4), 512, smemAttn>>>();
    outproj_kernel<<<dim3(192, 4), 256, smemProj>>>(Wout, bout, out);
}

// round 2
// speedup vs baseline: 2.0873x; 2.0873x over previous
#include <cuda_runtime.h>

typedef unsigned long long u64;

// Problem dims
#define B_ 2
#define N_ 512
#define T_ 12
#define E_ 128
#define H_ 8
#define D_ 16
#define BHT 192                // B*H*T
#define SLICE 8192             // N*D
#define HEADSZ (BHT*SLICE)
#define MROWS (B_*N_*T_)       // 12288

// Scratch: heads layout [B,H,T,N,D]
// 0:Qf 1:Kf 2:Vf 3:Qs 4:Ks 5:Vs 6:Qfs
__device__ float g_heads[7][HEADSZ];
__device__ float g_ctx[4][HEADSZ];

// ---- packed fp32x2 helpers (Blackwell FFMA2 path) ----
__device__ __forceinline__ u64 pack2(float lo, float hi) {
    u64 r; asm("mov.b64 %0,{%1,%2};" : "=l"(r) : "f"(lo), "f"(hi)); return r;
}
__device__ __forceinline__ void unpack2(u64 v, float& lo, float& hi) {
    asm("mov.b64 {%0,%1},%2;" : "=f"(lo), "=f"(hi) : "l"(v));
}
__device__ __forceinline__ u64 fma2(u64 a, u64 b, u64 c) {
    u64 d; asm("fma.rn.f32x2 %0,%1,%2,%3;" : "=l"(d) : "l"(a), "l"(b), "l"(c)); return d;
}
__device__ __forceinline__ u64 mul2(u64 a, u64 b) {
    u64 d; asm("mul.rn.f32x2 %0,%1,%2;" : "=l"(d) : "l"(a), "l"(b)); return d;
}
__device__ __forceinline__ u64 add2(u64 a, u64 b) {
    u64 d; asm("add.rn.f32x2 %0,%1,%2;" : "=l"(d) : "l"(a), "l"(b)); return d;
}

struct ProjArgs {
    const float* x[6];
    const float* w[6];
    const float* kj;
    const float* vfp;
};

// ---------------------------------------------------------------------------
// Kernel 1: input projections. y = x @ W, scatter to heads layout.
// W pre-packed in smem as u64 pairs (col c, col c+64): conflict-free LDS.64.
// ---------------------------------------------------------------------------
__global__ __launch_bounds__(256) void proj_kernel(ProjArgs args) {
    extern __shared__ float sm[];
    u64* Wp = (u64*)sm;              // 8192 u64 = 64KB
    float* Xs = sm + 16384;          // 64*128 floats = 32KB
    const int p = blockIdx.y;
    const int tile = blockIdx.x;
    const int tid = threadIdx.x;

    const float* W = args.w[p];
    const float* X = args.x[p] + (size_t)tile * 64 * 128;

    for (int q = tid; q < 8192; q += 256) {
        int k = q >> 6, c = q & 63;
        Wp[q] = pack2(W[k * 128 + c], W[k * 128 + c + 64]);
    }
    for (int i = tid; i < 2048; i += 256)
        ((float4*)Xs)[i] = ((const float4*)X)[i];
    __syncthreads();

    const int cg = tid & 15;         // d index / column group
    const int rg = tid >> 4;
    const int r0 = rg << 2;

    u64 acc[4][4];
#pragma unroll
    for (int i = 0; i < 4; i++)
#pragma unroll
        for (int j = 0; j < 4; j++) acc[i][j] = 0ull;

    for (int k0 = 0; k0 < 128; k0 += 4) {
        float4 xv[4];
#pragma unroll
        for (int i = 0; i < 4; i++)
            xv[i] = *(const float4*)&Xs[(r0 + i) * 128 + k0];
#pragma unroll
        for (int kk = 0; kk < 4; kk++) {
            u64 w4[4];
#pragma unroll
            for (int j = 0; j < 4; j++)
                w4[j] = Wp[(k0 + kk) * 64 + cg + 16 * j];
#pragma unroll
            for (int i = 0; i < 4; i++) {
                float xc = (kk == 0) ? xv[i].x : (kk == 1) ? xv[i].y : (kk == 2) ? xv[i].z : xv[i].w;
                u64 xa = pack2(xc, xc);
#pragma unroll
                for (int j = 0; j < 4; j++)
                    acc[i][j] = fma2(xa, w4[j], acc[i][j]);
            }
        }
    }

    const bool isQs = (p == 3);
#pragma unroll
    for (int i = 0; i < 4; i++) {
        int row = tile * 64 + r0 + i;
        int t = row % T_;
        int n = (row / T_) % N_;
        int b = row / (T_ * N_);
        float kj = 0.f, vfpi = 1.f;
        if (isQs) { kj = args.kj[n]; vfpi = args.vfp[n] + 1e-5f; }
#pragma unroll
        for (int j = 0; j < 4; j++) {
            float vlo, vhi; unpack2(acc[i][j], vlo, vhi);
            int h0 = j, h1 = j + 4;                    // c = cg+16j and +64
            int idx0 = (((b * H_ + h0) * T_ + t) * N_ + n) * D_ + cg;
            int idx1 = (((b * H_ + h1) * T_ + t) * N_ + n) * D_ + cg;
            g_heads[p][idx0] = vlo;
            g_heads[p][idx1] = vhi;
            if (isQs) {
                g_heads[6][idx0] = kj * (vlo - vlo * vlo / vfpi);
                g_heads[6][idx1] = kj * (vhi - vhi * vhi / vfpi);
            }
        }
    }
}

// ---------------------------------------------------------------------------
// Kernel 2: attention. One block per (slice, att). 512 threads = 16 warps.
// Each warp owns 4 query rows per pass (8 passes). K/V rows amortized 4x.
// Raw scores -> smem; exp fused into PV pass; f32x2 FMA throughout.
// ---------------------------------------------------------------------------
__global__ __launch_bounds__(512) void attn_kernel() {
    extern __shared__ float sm[];
    float* Bs = sm;                  // 512*20
    float* Vs = sm + 10240;          // 512*20
    float* Sc = sm + 20480;          // 64*528

    const int slice = blockIdx.x;    // 0..191
    const int att = blockIdx.y;      // 0..3

    int ai, bi, vi;
    switch (att) {
        case 0:  ai = 0; bi = 1; vi = 2; break;  // ff: Qf,Kf,Vf
        case 1:  ai = 1; bi = 6; vi = 2; break;  // fs: Kf,Qfs,Vf
        case 2:  ai = 4; bi = 0; vi = 5; break;  // sf: Ks,Qf,Vs
        default: ai = 3; bi = 4; vi = 5; break;  // ss: Qs,Ks,Vs
    }

    const float* Ag = g_heads[ai] + slice * SLICE;
    const float* Bg = g_heads[bi] + slice * SLICE;
    const float* Vg = g_heads[vi] + slice * SLICE;
    float* Og = g_ctx[att] + slice * SLICE;

    const int tid = threadIdx.x;
    for (int i = tid; i < 2048; i += 512) {
        int r = i >> 2, s4 = i & 3;
        ((float4*)&Bs[r * 20])[s4] = ((const float4*)Bg)[i];
        ((float4*)&Vs[r * 20])[s4] = ((const float4*)Vg)[i];
    }
    __syncthreads();

    const int w = tid >> 5;
    const int lane = tid & 31;
    float* ScW = Sc + (w * 4) * 528;  // this warp's private 4-row score area

    for (int pass = 0; pass < 8; pass++) {
        const int n0 = pass * 64 + w * 4;

        // ---- P1: scores + row max ----
        u64 a[4][8];
#pragma unroll
        for (int r = 0; r < 4; r++) {
            const u64* Ar = (const u64*)(Ag + (n0 + r) * 16);
#pragma unroll
            for (int j = 0; j < 8; j++) a[r][j] = Ar[j];
        }
        float mx[4] = {-3.0e38f, -3.0e38f, -3.0e38f, -3.0e38f};
#pragma unroll 4
        for (int k = 0; k < 16; k++) {
            int m = lane + 32 * k;
            const ulonglong2* Br = (const ulonglong2*)&Bs[m * 20];
            ulonglong2 b01 = Br[0], b23 = Br[1], b45 = Br[2], b67 = Br[3];
            u64 bb[8] = {b01.x, b01.y, b23.x, b23.y, b45.x, b45.y, b67.x, b67.y};
#pragma unroll
            for (int r = 0; r < 4; r++) {
                u64 s2 = mul2(a[r][0], bb[0]);
#pragma unroll
                for (int j = 1; j < 8; j++) s2 = fma2(a[r][j], bb[j], s2);
                float lo, hi; unpack2(s2, lo, hi);
                float s = (lo + hi) * 0.25f;
                ScW[r * 528 + m] = s;
                mx[r] = fmaxf(mx[r], s);
            }
        }
#pragma unroll
        for (int r = 0; r < 4; r++) {
            mx[r] = fmaxf(mx[r], __shfl_xor_sync(0xffffffffu, mx[r], 16));
            mx[r] = fmaxf(mx[r], __shfl_xor_sync(0xffffffffu, mx[r], 8));
            mx[r] = fmaxf(mx[r], __shfl_xor_sync(0xffffffffu, mx[r], 4));
            mx[r] = fmaxf(mx[r], __shfl_xor_sync(0xffffffffu, mx[r], 2));
            mx[r] = fmaxf(mx[r], __shfl_xor_sync(0xffffffffu, mx[r], 1));
        }

        // ---- P3: exp fused + PV accumulate + sum ----
        u64 acc[4][8];
#pragma unroll
        for (int r = 0; r < 4; r++)
#pragma unroll
            for (int j = 0; j < 8; j++) acc[r][j] = 0ull;
        float sum[4] = {0.f, 0.f, 0.f, 0.f};
#pragma unroll 4
        for (int k = 0; k < 16; k++) {
            int m = lane + 32 * k;
            float pe[4];
#pragma unroll
            for (int r = 0; r < 4; r++) {
                pe[r] = __expf(ScW[r * 528 + m] - mx[r]);
                sum[r] += pe[r];
            }
            const ulonglong2* Vr = (const ulonglong2*)&Vs[m * 20];
            ulonglong2 v01 = Vr[0], v23 = Vr[1], v45 = Vr[2], v67 = Vr[3];
            u64 vv[8] = {v01.x, v01.y, v23.x, v23.y, v45.x, v45.y, v67.x, v67.y};
#pragma unroll
            for (int r = 0; r < 4; r++) {
                u64 pp = pack2(pe[r], pe[r]);
#pragma unroll
                for (int j = 0; j < 8; j++)
                    acc[r][j] = fma2(pp, vv[j], acc[r][j]);
            }
        }
#pragma unroll
        for (int r = 0; r < 4; r++) {
            sum[r] += __shfl_xor_sync(0xffffffffu, sum[r], 16);
            sum[r] += __shfl_xor_sync(0xffffffffu, sum[r], 8);
            sum[r] += __shfl_xor_sync(0xffffffffu, sum[r], 4);
            sum[r] += __shfl_xor_sync(0xffffffffu, sum[r], 2);
            sum[r] += __shfl_xor_sync(0xffffffffu, sum[r], 1);
        }

        // ---- cross-lane acc reduction via conflict-free smem scratch ----
        u64* scr = (u64*)ScW;        // 4*528 floats = 1056 u64 = 32*33 exactly
        __syncwarp();
#pragma unroll
        for (int v = 0; v < 32; v++)
            scr[lane * 33 + v] = acc[v >> 3][v & 7];
        __syncwarp();
        u64 tot = scr[lane];
#pragma unroll 8
        for (int l2 = 1; l2 < 32; l2++)
            tot = add2(tot, scr[l2 * 33 + lane]);

        int r = lane >> 3, j = lane & 7;
        float inv = 1.0f / sum[r];
        float lo, hi; unpack2(tot, lo, hi);
        *(float2*)&Og[(n0 + r) * 16 + j * 2] = make_float2(lo * inv, hi * inv);
        __syncwarp();
    }
}

// ---------------------------------------------------------------------------
// Kernel 3: output projection. Gather ctx -> [B,N,T,E] rows, GEMM Wout, +bias.
// ---------------------------------------------------------------------------
__global__ __launch_bounds__(256) void outproj_kernel(
    const float* __restrict__ Wout, const float* __restrict__ bout,
    float* __restrict__ out) {
    extern __shared__ float sm[];
    u64* Wp = (u64*)sm;              // 8192 u64 = 64KB
    float* Xs = sm + 16384;          // 64*128 floats
    const int att = blockIdx.y;
    const int tile = blockIdx.x;
    const int tid = threadIdx.x;

    for (int q = tid; q < 8192; q += 256) {
        int k = q >> 6, c = q & 63;
        Wp[q] = pack2(Wout[k * 128 + c], Wout[k * 128 + c + 64]);
    }

    const float* ctx = g_ctx[att];
    for (int i = tid; i < 2048; i += 256) {
        int rr = i >> 5;
        int f4 = i & 31;
        int row = tile * 64 + rr;
        int t = row % T_;
        int n = (row / T_) % N_;
        int b = row / (T_ * N_);
        int h = f4 >> 2;
        int ds = (f4 & 3) << 2;
        int idx = (((b * H_ + h) * T_ + t) * N_ + n) * D_ + ds;
        *(float4*)&Xs[rr * 128 + (f4 << 2)] = *(const float4*)&ctx[idx];
    }
    __syncthreads();

    const int cg = tid & 15;
    const int rg = tid >> 4;
    const int r0 = rg << 2;

    u64 acc[4][4];
#pragma unroll
    for (int i = 0; i < 4; i++)
#pragma unroll
        for (int j = 0; j < 4; j++) acc[i][j] = 0ull;

    for (int k0 = 0; k0 < 128; k0 += 4) {
        float4 xv[4];
#pragma unroll
        for (int i = 0; i < 4; i++)
            xv[i] = *(const float4*)&Xs[(r0 + i) * 128 + k0];
#pragma unroll
        for (int kk = 0; kk < 4; kk++) {
            u64 w4[4];
#pragma unroll
            for (int j = 0; j < 4; j++)
                w4[j] = Wp[(k0 + kk) * 64 + cg + 16 * j];
#pragma unroll
            for (int i = 0; i < 4; i++) {
                float xc = (kk == 0) ? xv[i].x : (kk == 1) ? xv[i].y : (kk == 2) ? xv[i].z : xv[i].w;
                u64 xa = pack2(xc, xc);
#pragma unroll
                for (int j = 0; j < 4; j++)
                    acc[i][j] = fma2(xa, w4[j], acc[i][j]);
            }
        }
    }

    float blo[4], bhi[4];
#pragma unroll
    for (int j = 0; j < 4; j++) {
        blo[j] = __ldg(&bout[cg + 16 * j]);
        bhi[j] = __ldg(&bout[cg + 16 * j + 64]);
    }

    float* outp = out + (size_t)att * MROWS * E_;
#pragma unroll
    for (int i = 0; i < 4; i++) {
        int row = tile * 64 + r0 + i;
#pragma unroll
        for (int j = 0; j < 4; j++) {
            float vlo, vhi; unpack2(acc[i][j], vlo, vhi);
            outp[row * 128 + cg + 16 * j]      = vlo + blo[j];
            outp[row * 128 + cg + 16 * j + 64] = vhi + bhi[j];
        }
    }
}

// ---------------------------------------------------------------------------
extern "C" void kernel_launch(void* const* d_in, const int* in_sizes, int n_in,
                              void* d_out, int out_size) {
    ProjArgs pa;
    for (int i = 0; i < 6; i++) {
        pa.x[i] = (const float*)d_in[i];
        pa.w[i] = (const float*)d_in[6 + i];
    }
    pa.kj  = (const float*)d_in[12];
    pa.vfp = (const float*)d_in[13];
    const float* Wout = (const float*)d_in[14];
    const float* bout = (const float*)d_in[15];
    float* out = (float*)d_out;

    const int smemProj = 98304;                     // 64KB Wp + 32KB Xs
    const int smemAttn = (20480 + 64 * 528) * 4;    // 217088 B

    cudaFuncSetAttribute(proj_kernel, cudaFuncAttributeMaxDynamicSharedMemorySize, smemProj);
    cudaFuncSetAttribute(attn_kernel, cudaFuncAttributeMaxDynamicSharedMemorySize, smemAttn);
    cudaFuncSetAttribute(outproj_kernel, cudaFuncAttributeMaxDynamicSharedMemorySize, smemProj);

    proj_kernel<<<dim3(192, 6), 256, smemProj>>>(pa);
    attn_kernel<<<dim3(192, 4), 512, smemAttn>>>();
    outproj_kernel<<<dim3(192, 4), 256, smemProj>>>(Wout, bout, out);
}